// round 12
// baseline (speedup 1.0000x reference)
#include <cuda_runtime.h>
#include <math.h>

#define BB 16
#define SS 2048
#define DD 768
#define DD4 192          // DD/4
#define KW 3
#define ROW3 (DD*KW)     // 2304
#define NCHUNK 16
#define OPC (DD/NCHUNK)  // 48 output channels per chunk
#define CH 8             // scan chunks per batch
#define CSZ (SS/CH)      // 256 steps per chunk
#define NBLK (BB*CH)     // 128 scan blocks

// ---- scratch (no allocations allowed; .bss-zeroed at load) ----
__device__ float  g_part[NCHUNK][ROW3];
__device__ float  g_weff[KW][DD];     // w_eff[k][d], d contiguous
__device__ float  g_beff;
__device__ float4 g_rx[BB*SS];        // shifted stencil: slot t = (r0[t-1], r1[t], r2[t+1], -)
__device__ double g_csum[NBLK];       // per-chunk alpha totals
__device__ double g_coff[NBLK];       // exclusive chunk offsets
__device__ float  g_wmain[BB*SS];
__device__ float  g_wspill[BB*SS];
__device__ int    g_firepos[BB*SS];   // per batch: step index of fire j
__device__ int    g_F[BB];            // number of fires per batch
__device__ int    g_arrive;           // grid-barrier ticket (self-resetting)
__device__ int    g_done;             // offsets-ready flag (self-resetting)
__device__ int    g_exit;             // exit ticket (self-resetting)

// ============================================================
// kA1: partial w_eff over o-chunks.  grid (9, 16) x 256
// conv_w (O,I,K): (o,d,k) at o*ROW3 + d*3 + k
// ============================================================
__global__ void kA1(const float* __restrict__ conv_w,
                    const float* __restrict__ lin_w) {
    int t  = blockIdx.x * blockDim.x + threadIdx.x;   // 0..2303
    int o0 = blockIdx.y * OPC;
    float acc = 0.f;
#pragma unroll 8
    for (int o = o0; o < o0 + OPC; ++o)
        acc += lin_w[o] * conv_w[o * ROW3 + t];
    g_part[blockIdx.y][t] = acc;
}

// kA2: combine partials (fixed order -> deterministic) + b_eff. grid 9 x 256
__global__ void kA2(const float* __restrict__ conv_b,
                    const float* __restrict__ lin_w,
                    const float* __restrict__ lin_b) {
    int t = blockIdx.x * blockDim.x + threadIdx.x;
    float s = 0.f;
#pragma unroll
    for (int c = 0; c < NCHUNK; ++c) s += g_part[c][t];
    g_weff[t % 3][t / 3] = s;

    if (blockIdx.x == 0) {
        __shared__ float red[256];
        float s2 = 0.f;
        for (int i = threadIdx.x; i < DD; i += 256)
            s2 += lin_w[i] * conv_b[i];
        red[threadIdx.x] = s2;
        __syncthreads();
        for (int st = 128; st > 0; st >>= 1) {
            if (threadIdx.x < st) red[threadIdx.x] += red[threadIdx.x + st];
            __syncthreads();
        }
        if (threadIdx.x == 0) g_beff = red[0] + lin_b[0];
    }
}

// ============================================================
// kB: r_k[b,t] = sum_d w_eff[d,k] * x[b,t,d].  One warp per row.
// Writes shifted slots so kC needs ONE float4 load per step.
// Rows with t > len[b] are dead -> early-out (slots stay 0; lens
// are replay-constant so the written set is identical every call).
// grid BB*SS/8 x 256
// ============================================================
__global__ void kB(const float* __restrict__ x, const int* __restrict__ lens) {
    int row  = blockIdx.x * 8 + (threadIdx.x >> 5);   // 0..BB*SS-1
    int lane = threadIdx.x & 31;
    int b = row >> 11;                 // row / SS
    int t = row & (SS - 1);
    if (t > __ldg(lens + b)) return;

    const float4* xr = (const float4*)(x) + (size_t)row * DD4;
    const float4* w0 = (const float4*)g_weff[0];
    const float4* w1 = (const float4*)g_weff[1];
    const float4* w2 = (const float4*)g_weff[2];
    float a0 = 0.f, a1 = 0.f, a2 = 0.f;
#pragma unroll
    for (int i = 0; i < 6; ++i) {
        int c = lane + i * 32;
        float4 xv = xr[c];
        float4 v0 = w0[c], v1 = w1[c], v2 = w2[c];
        a0 += xv.x*v0.x + xv.y*v0.y + xv.z*v0.z + xv.w*v0.w;
        a1 += xv.x*v1.x + xv.y*v1.y + xv.z*v1.z + xv.w*v1.w;
        a2 += xv.x*v2.x + xv.y*v2.y + xv.z*v2.z + xv.w*v2.w;
    }
#pragma unroll
    for (int off = 16; off > 0; off >>= 1) {
        a0 += __shfl_down_sync(0xffffffffu, a0, off);
        a1 += __shfl_down_sync(0xffffffffu, a1, off);
        a2 += __shfl_down_sync(0xffffffffu, a2, off);
    }
    if (lane == 0) {
        g_rx[row].y = a1;                        // r1[t] -> slot t
        if (t + 1 < SS) g_rx[row + 1].x = a0;    // r0[t] -> slot t+1
        if (t > 0)      g_rx[row - 1].z = a2;    // r2[t] -> slot t-1
    }
}

// ============================================================
// kC: fused cooperative scan.  grid NBLK x 256, 1 step/thread,
// all blocks resident (128 <= 148 SMs) -> software grid barrier.
// Phase 1: alpha + block scan + publish chunk total.
// Barrier: last arriver's threads 0..15 do per-batch serial
//          chunk-offset scans (fixed order), then release.
// Phase 2: add offset, emit weights/firepos.
// ============================================================
__global__ void kC(const int* __restrict__ lens, float* __restrict__ lens_out) {
    __shared__ double wt[8], wo[8];
    __shared__ bool is_writer;
    int blk = blockIdx.x;              // b*CH + c
    int b   = blk >> 3;
    int c   = blk & 7;
    int tid = threadIdx.x;             // 0..255
    int t   = c * CSZ + tid;
    int len = lens[b];
    int base = b * SS;

    // ---- alpha (register-resident) ----
    float a = 0.f;
    if (t < len) {
        float4 rx = g_rx[base + t];
        float logit = g_beff + rx.x + rx.y + rx.z;
        a = 1.f / (1.f + expf(-logit));
    }

    // ---- block-local fp64 inclusive scan (8 warps) ----
    double v = (double)a;
    int lane = tid & 31, wid = tid >> 5;
#pragma unroll
    for (int off = 1; off < 32; off <<= 1) {
        double n = __shfl_up_sync(0xffffffffu, v, off);
        if (lane >= off) v += n;
    }
    if (lane == 31) wt[wid] = v;
    __syncthreads();
    if (tid == 0) {
        double run = 0.0;
#pragma unroll
        for (int w = 0; w < 8; ++w) { wo[w] = run; run += wt[w]; }
        // ---- publish chunk total, arrive at grid barrier ----
        g_csum[blk] = run;
        __threadfence();
        is_writer = (atomicAdd(&g_arrive, 1) == NBLK - 1);
    }
    __syncthreads();

    if (is_writer) {
        if (tid < BB) {                // 16 threads: serial per-batch chunk scan
            double run = 0.0;
#pragma unroll
            for (int cc = 0; cc < CH; ++cc) {
                g_coff[tid * CH + cc] = run;
                run += g_csum[tid * CH + cc];
            }
            int F = (int)floor(run);
            g_F[tid] = F;
            if (lens_out) lens_out[tid] = (float)F;
        }
        __syncthreads();
        if (tid == 0) { __threadfence(); atomicExch(&g_done, 1); }
    } else if (tid == 0) {
        while (atomicAdd(&g_done, 0) == 0) { }
    }
    __syncthreads();

    // ---- phase 2: global positions + emit ----
    if (t < len) {
        double coff = g_coff[blk];
        double Ci = coff + wo[wid] + v;          // inclusive at t
        double Ce = Ci - (double)a;              // exclusive
        double fp = floor(Ce);
        double fc = floor(Ci);
        float w1, w2 = 0.f;
        if (fc > fp) {                           // fire (alpha<1 => fc == fp+1)
            float aaccf = (float)(Ce - fp);      // reference-style f32 aacc
            w1 = 1.0f - aaccf;
            w2 = a - w1;
            g_firepos[base + (int)fp] = t;
        } else {
            w1 = a;
        }
        g_wmain[base + t]  = w1;
        g_wspill[base + t] = w2;
    }

    // ---- reset barrier state for next graph replay ----
    __syncthreads();
    if (tid == 0) {
        if (atomicAdd(&g_exit, 1) == NBLK - 1) {
            g_arrive = 0; g_done = 0; g_exit = 0;
            __threadfence();
        }
    }
}

// ============================================================
// kD: output row (b,j) = segmented weighted sum, same t-order as reference.
// grid (SS, BB) x 192 threads (one float4 column per thread).
// ============================================================
__global__ void kD(const float* __restrict__ x, float* __restrict__ out) {
    int j = blockIdx.x, b = blockIdx.y;
    int i = threadIdx.x;                  // 0..191
    float4* o4 = (float4*)out + (size_t)(b * SS + j) * DD4 + i;
    int F = g_F[b];
    if (j >= F) { *o4 = make_float4(0.f, 0.f, 0.f, 0.f); return; }

    int p1 = g_firepos[b * SS + j];
    int p0 = (j == 0) ? 0 : g_firepos[b * SS + j - 1];
    const float4* x4 = (const float4*)x + (size_t)b * SS * DD4 + i;

    float4 acc = make_float4(0.f, 0.f, 0.f, 0.f);
    int t = p0;
    if (j > 0) {                          // spill a2*h from previous fire step
        float w = g_wspill[b * SS + p0];
        float4 h = __ldg(x4 + (size_t)p0 * DD4);
        acc.x = w * h.x; acc.y = w * h.y; acc.z = w * h.z; acc.w = w * h.w;
        t = p0 + 1;
    }
#pragma unroll 4
    for (; t <= p1; ++t) {                // interior a*h ... then a1*h at fire
        float w = g_wmain[b * SS + t];
        float4 h = __ldg(x4 + (size_t)t * DD4);
        acc.x += w * h.x; acc.y += w * h.y; acc.z += w * h.z; acc.w += w * h.w;
    }
    *o4 = acc;
}

// ============================================================
extern "C" void kernel_launch(void* const* d_in, const int* in_sizes, int n_in,
                              void* d_out, int out_size) {
    const float* x      = (const float*)d_in[0];   // encoder_outputs (B,S,D)
    const int*   lens   = (const int*)  d_in[1];   // encoder_lens (B,)
    const float* conv_w = (const float*)d_in[2];   // (D,D,3)
    const float* conv_b = (const float*)d_in[3];   // (D,)
    const float* lin_w  = (const float*)d_in[4];   // (1,D)
    const float* lin_b  = (const float*)d_in[5];   // (1,)
    float* out = (float*)d_out;
    float* lens_out = (out_size >= BB * SS * DD + BB) ? out + (size_t)BB * SS * DD
                                                      : nullptr;

    kA1<<<dim3(ROW3 / 256, NCHUNK), 256>>>(conv_w, lin_w);
    kA2<<<ROW3 / 256, 256>>>(conv_b, lin_w, lin_b);
    kB <<<BB * SS / 8, 256>>>(x, lens);
    kC <<<NBLK, 256>>>(lens, lens_out);
    kD <<<dim3(SS, BB), 192>>>(x, out);
}

// round 13
// speedup vs baseline: 1.2705x; 1.2705x over previous
#include <cuda_runtime.h>
#include <math.h>

#define BB 16
#define SS 2048
#define DD 768
#define DD4 192          // DD/4
#define KW 3
#define ROW3 (DD*KW)     // 2304
#define NCHUNK 16
#define OPC (DD/NCHUNK)  // 48 output channels per chunk
#define CH 8             // scan chunks per batch
#define CSZ (SS/CH)      // 256 steps per chunk

// ---- scratch (no allocations allowed; .bss-zeroed at load) ----
__device__ float  g_part[NCHUNK][ROW3];
__device__ float  g_weff[KW][DD];     // w_eff[k][d], d contiguous
__device__ float  g_beff;
__device__ float4 g_rx[BB*SS];        // shifted stencil: slot t = (r0[t-1], r1[t], r2[t+1], -)
__device__ float  g_a[BB*SS];         // masked alphas
__device__ double g_csum[BB*CH];      // per-chunk alpha totals
__device__ float  g_wmain[BB*SS];
__device__ float  g_wspill[BB*SS];
__device__ int    g_firepos[BB*SS];   // per batch: step index of fire j
__device__ int    g_F[BB];            // number of fires per batch

// ============================================================
// kA1: partial w_eff over o-chunks.  grid (9, 16) x 256
// conv_w (O,I,K): (o,d,k) at o*ROW3 + d*3 + k
// ============================================================
__global__ void kA1(const float* __restrict__ conv_w,
                    const float* __restrict__ lin_w) {
    int t  = blockIdx.x * blockDim.x + threadIdx.x;   // 0..2303
    int o0 = blockIdx.y * OPC;
    float acc = 0.f;
#pragma unroll 8
    for (int o = o0; o < o0 + OPC; ++o)
        acc += lin_w[o] * conv_w[o * ROW3 + t];
    g_part[blockIdx.y][t] = acc;
}

// kA2: combine partials (fixed order -> deterministic) + b_eff. grid 9 x 256
__global__ void kA2(const float* __restrict__ conv_b,
                    const float* __restrict__ lin_w,
                    const float* __restrict__ lin_b) {
    int t = blockIdx.x * blockDim.x + threadIdx.x;
    float s = 0.f;
#pragma unroll
    for (int c = 0; c < NCHUNK; ++c) s += g_part[c][t];
    g_weff[t % 3][t / 3] = s;

    if (blockIdx.x == 0) {
        __shared__ float red[256];
        float s2 = 0.f;
        for (int i = threadIdx.x; i < DD; i += 256)
            s2 += lin_w[i] * conv_b[i];
        red[threadIdx.x] = s2;
        __syncthreads();
        for (int st = 128; st > 0; st >>= 1) {
            if (threadIdx.x < st) red[threadIdx.x] += red[threadIdx.x + st];
            __syncthreads();
        }
        if (threadIdx.x == 0) g_beff = red[0] + lin_b[0];
    }
}

// ============================================================
// kB: r_k[b,t] = sum_d w_eff[d,k] * x[b,t,d].  One warp per row.
// Writes shifted slots so kC1 needs ONE float4 load per step:
//   slot t .x = r0[t-1], .y = r1[t], .z = r2[t+1]
// Rows with t > len[b] are dead -> early-out (slots stay 0; lens
// are replay-constant so the written set is identical every call).
// grid BB*SS/8 x 256
// ============================================================
__global__ void kB(const float* __restrict__ x, const int* __restrict__ lens) {
    int row  = blockIdx.x * 8 + (threadIdx.x >> 5);   // 0..BB*SS-1
    int lane = threadIdx.x & 31;
    int b = row >> 11;                 // row / SS
    int t = row & (SS - 1);
    if (t > __ldg(lens + b)) return;

    const float4* xr = (const float4*)(x) + (size_t)row * DD4;
    const float4* w0 = (const float4*)g_weff[0];
    const float4* w1 = (const float4*)g_weff[1];
    const float4* w2 = (const float4*)g_weff[2];
    float a0 = 0.f, a1 = 0.f, a2 = 0.f;
#pragma unroll
    for (int i = 0; i < 6; ++i) {
        int c = lane + i * 32;
        float4 xv = xr[c];
        float4 v0 = w0[c], v1 = w1[c], v2 = w2[c];
        a0 += xv.x*v0.x + xv.y*v0.y + xv.z*v0.z + xv.w*v0.w;
        a1 += xv.x*v1.x + xv.y*v1.y + xv.z*v1.z + xv.w*v1.w;
        a2 += xv.x*v2.x + xv.y*v2.y + xv.z*v2.z + xv.w*v2.w;
    }
#pragma unroll
    for (int off = 16; off > 0; off >>= 1) {
        a0 += __shfl_down_sync(0xffffffffu, a0, off);
        a1 += __shfl_down_sync(0xffffffffu, a1, off);
        a2 += __shfl_down_sync(0xffffffffu, a2, off);
    }
    if (lane == 0) {
        g_rx[row].y = a1;                        // r1[t] -> slot t
        if (t + 1 < SS) g_rx[row + 1].x = a0;    // r0[t] -> slot t+1
        if (t > 0)      g_rx[row - 1].z = a2;    // r2[t] -> slot t-1
    }
}

// ============================================================
// kC1: alphas (1 float4 load) + per-chunk fp64 totals.
// grid BB*CH x 256 (1 step/thread).
// ============================================================
__global__ void kC1(const int* __restrict__ lens) {
    __shared__ double ws[8];
    int blk = blockIdx.x;              // b*CH + c
    int b   = blk >> 3;
    int c   = blk & 7;
    int tid = threadIdx.x;             // 0..255
    int t   = c * CSZ + tid;
    int len = lens[b];
    int base = b * SS;

    float a = 0.f;
    if (t < len) {
        float4 rx = g_rx[base + t];
        float logit = g_beff + rx.x + rx.y + rx.z;
        a = 1.f / (1.f + expf(-logit));
        g_a[base + t] = a;
    }

    double v = (double)a;
    int lane = tid & 31, wid = tid >> 5;
#pragma unroll
    for (int off = 16; off > 0; off >>= 1)
        v += __shfl_down_sync(0xffffffffu, v, off);
    if (lane == 0) ws[wid] = v;
    __syncthreads();
    if (tid == 0) {
        double s = 0.0;
#pragma unroll
        for (int w = 0; w < 8; ++w) s += ws[w];   // fixed order
        g_csum[blk] = s;
    }
}

// ============================================================
// kC3: chunk offset inline (<=7 predecessor sums, fixed order) +
// local fp64 pair scan, emit weights/firepos.  cix==CH-1 block also
// writes F and lens_out.  grid BB*CH x 128 (2 steps/thread).
// ============================================================
__global__ void kC3(const int* __restrict__ lens, float* __restrict__ lens_out) {
    __shared__ double wt[4], wo[4];
    __shared__ double s_off;
    int blk = blockIdx.x;
    int b   = blk >> 3;
    int cix = blk & 7;
    int tid = threadIdx.x;             // 0..127
    int len = lens[b];
    int base = b * SS;
    int tb  = cix * CSZ + tid * 2;

    // prologue: exclusive chunk offset (serial fixed order, <=7 adds)
    if (tid == 0) {
        double run = 0.0;
        for (int cc = 0; cc < cix; ++cc) run += g_csum[b * CH + cc];
        s_off = run;
        if (cix == CH - 1) {
            double total = run + g_csum[blk];
            int F = (int)floor(total);
            g_F[b] = F;
            if (lens_out) lens_out[b] = (float)F;
        }
    }

    float a[2];
    a[0] = (tb     < len) ? g_a[base + tb]     : 0.f;
    a[1] = (tb + 1 < len) ? g_a[base + tb + 1] : 0.f;

    double pair = (double)a[0] + (double)a[1];
    double v = pair;
    int lane = tid & 31, wid = tid >> 5;
#pragma unroll
    for (int off = 1; off < 32; off <<= 1) {
        double n = __shfl_up_sync(0xffffffffu, v, off);
        if (lane >= off) v += n;
    }
    if (lane == 31) wt[wid] = v;
    __syncthreads();
    if (tid == 0) {
        double run = 0.0;
#pragma unroll
        for (int w = 0; w < 4; ++w) { wo[w] = run; run += wt[w]; }
    }
    __syncthreads();

    if (tb >= len) return;             // dead pair: nothing downstream reads it

    double excl0 = s_off + wo[wid] + (v - pair);
    double C0 = excl0 + (double)a[0];
    double C1 = C0 + (double)a[1];
    double Ce[2] = {excl0, C0};
    double Ci[2] = {C0, C1};

    float w1v[2], w2v[2];
#pragma unroll
    for (int e = 0; e < 2; ++e) {
        int t = tb + e;
        double fp = floor(Ce[e]);
        double fc = floor(Ci[e]);
        float af = a[e];
        float w1, w2 = 0.f;
        if (fc > fp) {                      // fire (alpha<1 => fc == fp+1)
            float aaccf = (float)(Ce[e] - fp);   // reference-style f32 aacc
            w1 = 1.0f - aaccf;
            w2 = af - w1;
            g_firepos[base + (int)fp] = t;
        } else {
            w1 = af;
        }
        w1v[e] = w1; w2v[e] = w2;
    }
    *(float2*)(g_wmain  + base + tb) = make_float2(w1v[0], w1v[1]);
    *(float2*)(g_wspill + base + tb) = make_float2(w2v[0], w2v[1]);
}

// ============================================================
// kD: output row (b,j) = segmented weighted sum, same t-order as reference.
// grid (SS, BB) x 192 threads (one float4 column per thread).
// ============================================================
__global__ void kD(const float* __restrict__ x, float* __restrict__ out) {
    int j = blockIdx.x, b = blockIdx.y;
    int i = threadIdx.x;                  // 0..191
    float4* o4 = (float4*)out + (size_t)(b * SS + j) * DD4 + i;
    int F = g_F[b];
    if (j >= F) { *o4 = make_float4(0.f, 0.f, 0.f, 0.f); return; }

    int p1 = g_firepos[b * SS + j];
    int p0 = (j == 0) ? 0 : g_firepos[b * SS + j - 1];
    const float4* x4 = (const float4*)x + (size_t)b * SS * DD4 + i;

    float4 acc = make_float4(0.f, 0.f, 0.f, 0.f);
    int t = p0;
    if (j > 0) {                          // spill a2*h from previous fire step
        float w = g_wspill[b * SS + p0];
        float4 h = __ldg(x4 + (size_t)p0 * DD4);
        acc.x = w * h.x; acc.y = w * h.y; acc.z = w * h.z; acc.w = w * h.w;
        t = p0 + 1;
    }
#pragma unroll 4
    for (; t <= p1; ++t) {                // interior a*h ... then a1*h at fire
        float w = g_wmain[b * SS + t];
        float4 h = __ldg(x4 + (size_t)t * DD4);
        acc.x += w * h.x; acc.y += w * h.y; acc.z += w * h.z; acc.w += w * h.w;
    }
    *o4 = acc;
}

// ============================================================
extern "C" void kernel_launch(void* const* d_in, const int* in_sizes, int n_in,
                              void* d_out, int out_size) {
    const float* x      = (const float*)d_in[0];   // encoder_outputs (B,S,D)
    const int*   lens   = (const int*)  d_in[1];   // encoder_lens (B,)
    const float* conv_w = (const float*)d_in[2];   // (D,D,3)
    const float* conv_b = (const float*)d_in[3];   // (D,)
    const float* lin_w  = (const float*)d_in[4];   // (1,D)
    const float* lin_b  = (const float*)d_in[5];   // (1,)
    float* out = (float*)d_out;
    float* lens_out = (out_size >= BB * SS * DD + BB) ? out + (size_t)BB * SS * DD
                                                      : nullptr;

    kA1<<<dim3(ROW3 / 256, NCHUNK), 256>>>(conv_w, lin_w);
    kA2<<<ROW3 / 256, 256>>>(conv_b, lin_w, lin_b);
    kB <<<BB * SS / 8, 256>>>(x, lens);
    kC1<<<BB * CH, 256>>>(lens);
    kC3<<<BB * CH, 128>>>(lens, lens_out);
    kD <<<dim3(SS, BB), 192>>>(x, out);
}

// round 14
// speedup vs baseline: 1.3080x; 1.0295x over previous
#include <cuda_runtime.h>
#include <cooperative_groups.h>
#include <math.h>

namespace cg = cooperative_groups;

#define BB 16
#define SS 2048
#define DD 768
#define DD4 192          // DD/4
#define KW 3
#define ROW3 (DD*KW)     // 2304
#define NCHUNK 16
#define OPC (DD/NCHUNK)  // 48 output channels per chunk
#define CH 8             // scan chunks per batch = cluster size
#define CSZ (SS/CH)      // 256 steps per chunk

// ---- scratch (no allocations allowed; .bss-zeroed at load) ----
__device__ float  g_part[NCHUNK][ROW3];
__device__ float  g_weff[KW][DD];     // w_eff[k][d], d contiguous
__device__ float  g_beff;
__device__ float4 g_rx[BB*SS];        // shifted stencil: slot t = (r0[t-1], r1[t], r2[t+1], -)
__device__ float  g_wmain[BB*SS];
__device__ float  g_wspill[BB*SS];
__device__ int    g_firepos[BB*SS];   // per batch: step index of fire j
__device__ int    g_F[BB];            // number of fires per batch

// ============================================================
// kA1: partial w_eff over o-chunks.  grid (9, 16) x 256
// conv_w (O,I,K): (o,d,k) at o*ROW3 + d*3 + k
// ============================================================
__global__ void kA1(const float* __restrict__ conv_w,
                    const float* __restrict__ lin_w) {
    int t  = blockIdx.x * blockDim.x + threadIdx.x;   // 0..2303
    int o0 = blockIdx.y * OPC;
    float acc = 0.f;
#pragma unroll 8
    for (int o = o0; o < o0 + OPC; ++o)
        acc += lin_w[o] * conv_w[o * ROW3 + t];
    g_part[blockIdx.y][t] = acc;
}

// kA2: combine partials (fixed order -> deterministic) + b_eff. grid 9 x 256
__global__ void kA2(const float* __restrict__ conv_b,
                    const float* __restrict__ lin_w,
                    const float* __restrict__ lin_b) {
    int t = blockIdx.x * blockDim.x + threadIdx.x;
    float s = 0.f;
#pragma unroll
    for (int c = 0; c < NCHUNK; ++c) s += g_part[c][t];
    g_weff[t % 3][t / 3] = s;

    if (blockIdx.x == 0) {
        __shared__ float red[256];
        float s2 = 0.f;
        for (int i = threadIdx.x; i < DD; i += 256)
            s2 += lin_w[i] * conv_b[i];
        red[threadIdx.x] = s2;
        __syncthreads();
        for (int st = 128; st > 0; st >>= 1) {
            if (threadIdx.x < st) red[threadIdx.x] += red[threadIdx.x + st];
            __syncthreads();
        }
        if (threadIdx.x == 0) g_beff = red[0] + lin_b[0];
    }
}

// ============================================================
// kB: r_k[b,t] = sum_d w_eff[d,k] * x[b,t,d].  One warp per row.
// Writes shifted slots so kC needs ONE float4 load per step:
//   slot t .x = r0[t-1], .y = r1[t], .z = r2[t+1]
// Rows with t > len[b] are dead -> early-out (slots stay 0; lens
// are replay-constant so the written set is identical every call).
// grid BB*SS/8 x 256
// ============================================================
__global__ void kB(const float* __restrict__ x, const int* __restrict__ lens) {
    int row  = blockIdx.x * 8 + (threadIdx.x >> 5);   // 0..BB*SS-1
    int lane = threadIdx.x & 31;
    int b = row >> 11;                 // row / SS
    int t = row & (SS - 1);
    if (t > __ldg(lens + b)) return;

    const float4* xr = (const float4*)(x) + (size_t)row * DD4;
    const float4* w0 = (const float4*)g_weff[0];
    const float4* w1 = (const float4*)g_weff[1];
    const float4* w2 = (const float4*)g_weff[2];
    float a0 = 0.f, a1 = 0.f, a2 = 0.f;
#pragma unroll
    for (int i = 0; i < 6; ++i) {
        int c = lane + i * 32;
        float4 xv = xr[c];
        float4 v0 = w0[c], v1 = w1[c], v2 = w2[c];
        a0 += xv.x*v0.x + xv.y*v0.y + xv.z*v0.z + xv.w*v0.w;
        a1 += xv.x*v1.x + xv.y*v1.y + xv.z*v1.z + xv.w*v1.w;
        a2 += xv.x*v2.x + xv.y*v2.y + xv.z*v2.z + xv.w*v2.w;
    }
#pragma unroll
    for (int off = 16; off > 0; off >>= 1) {
        a0 += __shfl_down_sync(0xffffffffu, a0, off);
        a1 += __shfl_down_sync(0xffffffffu, a1, off);
        a2 += __shfl_down_sync(0xffffffffu, a2, off);
    }
    if (lane == 0) {
        g_rx[row].y = a1;                        // r1[t] -> slot t
        if (t + 1 < SS) g_rx[row + 1].x = a0;    // r0[t] -> slot t+1
        if (t > 0)      g_rx[row - 1].z = a2;    // r2[t] -> slot t-1
    }
}

// ============================================================
// kCc: fused clustered scan.  grid BB*CH x 256, cluster (8,1,1):
// one cluster per batch; cluster rank == chunk index cix.
// alpha (1 float4 load) -> fp64 block scan -> DSMEM-broadcast chunk
// totals -> cluster.sync -> fixed-order offset -> emit.
// ============================================================
__global__ void __cluster_dims__(CH, 1, 1)
kCc(const int* __restrict__ lens, float* __restrict__ lens_out) {
    __shared__ double wt[8], wo[8];
    __shared__ double ctot[CH];        // peer chunk totals (slot = peer cix)
    __shared__ double s_tot, s_off;

    cg::cluster_group cl = cg::this_cluster();

    int blk = blockIdx.x;              // b*CH + cix
    int b   = blk >> 3;
    int cix = blk & 7;                 // == cluster block rank
    int tid = threadIdx.x;             // 0..255
    int t   = cix * CSZ + tid;
    int len = lens[b];
    int base = b * SS;

    // ---- alpha (register-resident, single float4 load) ----
    float a = 0.f;
    if (t < len) {
        float4 rx = g_rx[base + t];
        float logit = g_beff + rx.x + rx.y + rx.z;
        a = 1.f / (1.f + expf(-logit));
    }

    // ---- block-local fp64 inclusive scan (8 warps) ----
    double v = (double)a;
    int lane = tid & 31, wid = tid >> 5;
#pragma unroll
    for (int off = 1; off < 32; off <<= 1) {
        double n = __shfl_up_sync(0xffffffffu, v, off);
        if (lane >= off) v += n;
    }
    if (lane == 31) wt[wid] = v;
    __syncthreads();
    if (tid == 0) {
        double run = 0.0;
#pragma unroll
        for (int w = 0; w < 8; ++w) { wo[w] = run; run += wt[w]; }
        s_tot = run;                   // this chunk's total
    }
    __syncthreads();

    // ---- broadcast chunk total to slot[cix] of every peer's smem ----
    if (tid < CH) {
        double* peer = cl.map_shared_rank(ctot, tid);
        peer[cix] = s_tot;
    }
    cl.sync();

    // ---- fixed-order exclusive chunk offset (deterministic) ----
    if (tid == 0) {
        double run = 0.0;
#pragma unroll
        for (int cc = 0; cc < CH; ++cc) {
            if (cc == cix) { s_off = run; }
            run += ctot[cc];
        }
        if (cix == CH - 1) {           // total fires for this batch
            int F = (int)floor(run);
            g_F[b] = F;
            if (lens_out) lens_out[b] = (float)F;
        }
    }
    __syncthreads();

    // ---- emit weights / fire positions ----
    if (t < len) {
        double Ci = s_off + wo[wid] + v;         // inclusive at t
        double Ce = Ci - (double)a;              // exclusive
        double fp = floor(Ce);
        double fc = floor(Ci);
        float w1, w2 = 0.f;
        if (fc > fp) {                           // fire (alpha<1 => fc == fp+1)
            float aaccf = (float)(Ce - fp);      // reference-style f32 aacc
            w1 = 1.0f - aaccf;
            w2 = a - w1;
            g_firepos[base + (int)fp] = t;
        } else {
            w1 = a;
        }
        g_wmain[base + t]  = w1;
        g_wspill[base + t] = w2;
    }
}

// ============================================================
// kD: output row (b,j) = segmented weighted sum, same t-order as reference.
// grid (SS, BB) x 192 threads (one float4 column per thread).
// ============================================================
__global__ void kD(const float* __restrict__ x, float* __restrict__ out) {
    int j = blockIdx.x, b = blockIdx.y;
    int i = threadIdx.x;                  // 0..191
    float4* o4 = (float4*)out + (size_t)(b * SS + j) * DD4 + i;
    int F = g_F[b];
    if (j >= F) { *o4 = make_float4(0.f, 0.f, 0.f, 0.f); return; }

    int p1 = g_firepos[b * SS + j];
    int p0 = (j == 0) ? 0 : g_firepos[b * SS + j - 1];
    const float4* x4 = (const float4*)x + (size_t)b * SS * DD4 + i;

    float4 acc = make_float4(0.f, 0.f, 0.f, 0.f);
    int t = p0;
    if (j > 0) {                          // spill a2*h from previous fire step
        float w = g_wspill[b * SS + p0];
        float4 h = __ldg(x4 + (size_t)p0 * DD4);
        acc.x = w * h.x; acc.y = w * h.y; acc.z = w * h.z; acc.w = w * h.w;
        t = p0 + 1;
    }
#pragma unroll 4
    for (; t <= p1; ++t) {                // interior a*h ... then a1*h at fire
        float w = g_wmain[b * SS + t];
        float4 h = __ldg(x4 + (size_t)t * DD4);
        acc.x += w * h.x; acc.y += w * h.y; acc.z += w * h.z; acc.w += w * h.w;
    }
    *o4 = acc;
}

// ============================================================
extern "C" void kernel_launch(void* const* d_in, const int* in_sizes, int n_in,
                              void* d_out, int out_size) {
    const float* x      = (const float*)d_in[0];   // encoder_outputs (B,S,D)
    const int*   lens   = (const int*)  d_in[1];   // encoder_lens (B,)
    const float* conv_w = (const float*)d_in[2];   // (D,D,3)
    const float* conv_b = (const float*)d_in[3];   // (D,)
    const float* lin_w  = (const float*)d_in[4];   // (1,D)
    const float* lin_b  = (const float*)d_in[5];   // (1,)
    float* out = (float*)d_out;
    float* lens_out = (out_size >= BB * SS * DD + BB) ? out + (size_t)BB * SS * DD
                                                      : nullptr;

    kA1<<<dim3(ROW3 / 256, NCHUNK), 256>>>(conv_w, lin_w);
    kA2<<<ROW3 / 256, 256>>>(conv_b, lin_w, lin_b);
    kB <<<BB * SS / 8, 256>>>(x, lens);
    kCc<<<BB * CH, 256>>>(lens, lens_out);
    kD <<<dim3(SS, BB), 192>>>(x, out);
}

// round 15
// speedup vs baseline: 1.3322x; 1.0185x over previous
#include <cuda_runtime.h>
#include <cooperative_groups.h>
#include <math.h>

namespace cg = cooperative_groups;

#define BB 16
#define SS 2048
#define DD 768
#define DD4 192          // DD/4
#define KW 3
#define ROW3 (DD*KW)     // 2304
#define CH 8             // scan chunks per batch = cluster size
#define CSZ (SS/CH)      // 256 steps per chunk
#define TPB_A 32         // t-values per kA block
#define OG 8             // o-groups per kA block
#define OPG (DD/OG)      // 96 o's per group

// ---- scratch (no allocations allowed; .bss-zeroed at load) ----
__device__ float  g_weff[KW][DD];     // w_eff[k][d], d contiguous
__device__ float  g_beff;
__device__ float4 g_rx[BB*SS];        // shifted stencil: slot t = (r0[t-1], r1[t], r2[t+1], -)
__device__ float  g_wmain[BB*SS];
__device__ float  g_wspill[BB*SS];
__device__ int    g_firepos[BB*SS];   // per batch: step index of fire j
__device__ int    g_F[BB];            // number of fires per batch

// ============================================================
// kA: fused w_eff + b_eff, ONE launch, no cross-block combine.
// grid 72 x 256.  Block bi owns t in [bi*32, bi*32+32).
// tid = t_local + 32*g: thread sums o in [g*96,(g+1)*96) for its t
// (warp = 32 consecutive t at fixed g -> coalesced 128B lines),
// then fixed-order smem combine of the 8 group partials per t.
// Block 0 also computes b_eff (deterministic tree reduce).
// conv_w (O,I,K): (o,d,k) at o*ROW3 + d*3 + k.
// ============================================================
__global__ void kA(const float* __restrict__ conv_w,
                   const float* __restrict__ conv_b,
                   const float* __restrict__ lin_w,
                   const float* __restrict__ lin_b) {
    __shared__ float sp[OG][TPB_A];
    int tl = threadIdx.x & 31;         // t_local
    int g  = threadIdx.x >> 5;         // o-group
    int t  = blockIdx.x * TPB_A + tl;  // 0..2303

    float acc = 0.f;
    int o0 = g * OPG;
#pragma unroll 8
    for (int o = o0; o < o0 + OPG; ++o)
        acc += __ldg(lin_w + o) * conv_w[o * ROW3 + t];
    sp[g][tl] = acc;
    __syncthreads();

    if (g == 0) {                      // fixed-order combine (deterministic)
        float s = 0.f;
#pragma unroll
        for (int gg = 0; gg < OG; ++gg) s += sp[gg][tl];
        g_weff[t % 3][t / 3] = s;
    }

    if (blockIdx.x == 0) {             // b_eff = lin_w . conv_b + lin_b
        __shared__ float red[256];
        float s2 = 0.f;
        for (int i = threadIdx.x; i < DD; i += 256)
            s2 += lin_w[i] * conv_b[i];
        red[threadIdx.x] = s2;
        __syncthreads();
        for (int st = 128; st > 0; st >>= 1) {
            if (threadIdx.x < st) red[threadIdx.x] += red[threadIdx.x + st];
            __syncthreads();
        }
        if (threadIdx.x == 0) g_beff = red[0] + lin_b[0];
    }
}

// ============================================================
// kB: r_k[b,t] = sum_d w_eff[d,k] * x[b,t,d].  One warp per row.
// Writes shifted slots so kCc needs ONE float4 load per step:
//   slot t .x = r0[t-1], .y = r1[t], .z = r2[t+1]
// Rows with t > len[b] are dead -> early-out (slots stay 0; lens
// are replay-constant so the written set is identical every call).
// grid BB*SS/8 x 256
// ============================================================
__global__ void kB(const float* __restrict__ x, const int* __restrict__ lens) {
    int row  = blockIdx.x * 8 + (threadIdx.x >> 5);   // 0..BB*SS-1
    int lane = threadIdx.x & 31;
    int b = row >> 11;                 // row / SS
    int t = row & (SS - 1);
    if (t > __ldg(lens + b)) return;

    const float4* xr = (const float4*)(x) + (size_t)row * DD4;
    const float4* w0 = (const float4*)g_weff[0];
    const float4* w1 = (const float4*)g_weff[1];
    const float4* w2 = (const float4*)g_weff[2];
    float a0 = 0.f, a1 = 0.f, a2 = 0.f;
#pragma unroll
    for (int i = 0; i < 6; ++i) {
        int c = lane + i * 32;
        float4 xv = xr[c];
        float4 v0 = w0[c], v1 = w1[c], v2 = w2[c];
        a0 += xv.x*v0.x + xv.y*v0.y + xv.z*v0.z + xv.w*v0.w;
        a1 += xv.x*v1.x + xv.y*v1.y + xv.z*v1.z + xv.w*v1.w;
        a2 += xv.x*v2.x + xv.y*v2.y + xv.z*v2.z + xv.w*v2.w;
    }
#pragma unroll
    for (int off = 16; off > 0; off >>= 1) {
        a0 += __shfl_down_sync(0xffffffffu, a0, off);
        a1 += __shfl_down_sync(0xffffffffu, a1, off);
        a2 += __shfl_down_sync(0xffffffffu, a2, off);
    }
    if (lane == 0) {
        g_rx[row].y = a1;                        // r1[t] -> slot t
        if (t + 1 < SS) g_rx[row + 1].x = a0;    // r0[t] -> slot t+1
        if (t > 0)      g_rx[row - 1].z = a2;    // r2[t] -> slot t-1
    }
}

// ============================================================
// kCc: fused clustered scan.  grid BB*CH x 256, cluster (8,1,1):
// one cluster per batch; cluster rank == chunk index cix.
// alpha (1 float4 load) -> fp64 block scan -> DSMEM-broadcast chunk
// totals -> cluster.sync -> fixed-order offset -> emit.
// ============================================================
__global__ void __cluster_dims__(CH, 1, 1)
kCc(const int* __restrict__ lens, float* __restrict__ lens_out) {
    __shared__ double wt[8], wo[8];
    __shared__ double ctot[CH];        // peer chunk totals (slot = peer cix)
    __shared__ double s_tot, s_off;

    cg::cluster_group cl = cg::this_cluster();

    int blk = blockIdx.x;              // b*CH + cix
    int b   = blk >> 3;
    int cix = blk & 7;                 // == cluster block rank
    int tid = threadIdx.x;             // 0..255
    int t   = cix * CSZ + tid;
    int len = lens[b];
    int base = b * SS;

    // ---- alpha (register-resident, single float4 load) ----
    float a = 0.f;
    if (t < len) {
        float4 rx = g_rx[base + t];
        float logit = g_beff + rx.x + rx.y + rx.z;
        a = 1.f / (1.f + expf(-logit));
    }

    // ---- block-local fp64 inclusive scan (8 warps) ----
    double v = (double)a;
    int lane = tid & 31, wid = tid >> 5;
#pragma unroll
    for (int off = 1; off < 32; off <<= 1) {
        double n = __shfl_up_sync(0xffffffffu, v, off);
        if (lane >= off) v += n;
    }
    if (lane == 31) wt[wid] = v;
    __syncthreads();
    if (tid == 0) {
        double run = 0.0;
#pragma unroll
        for (int w = 0; w < 8; ++w) { wo[w] = run; run += wt[w]; }
        s_tot = run;                   // this chunk's total
    }
    __syncthreads();

    // ---- broadcast chunk total to slot[cix] of every peer's smem ----
    if (tid < CH) {
        double* peer = cl.map_shared_rank(ctot, tid);
        peer[cix] = s_tot;
    }
    cl.sync();

    // ---- fixed-order exclusive chunk offset (deterministic) ----
    if (tid == 0) {
        double run = 0.0;
#pragma unroll
        for (int cc = 0; cc < CH; ++cc) {
            if (cc == cix) { s_off = run; }
            run += ctot[cc];
        }
        if (cix == CH - 1) {           // total fires for this batch
            int F = (int)floor(run);
            g_F[b] = F;
            if (lens_out) lens_out[b] = (float)F;
        }
    }
    __syncthreads();

    // ---- emit weights / fire positions ----
    if (t < len) {
        double Ci = s_off + wo[wid] + v;         // inclusive at t
        double Ce = Ci - (double)a;              // exclusive
        double fp = floor(Ce);
        double fc = floor(Ci);
        float w1, w2 = 0.f;
        if (fc > fp) {                           // fire (alpha<1 => fc == fp+1)
            float aaccf = (float)(Ce - fp);      // reference-style f32 aacc
            w1 = 1.0f - aaccf;
            w2 = a - w1;
            g_firepos[base + (int)fp] = t;
        } else {
            w1 = a;
        }
        g_wmain[base + t]  = w1;
        g_wspill[base + t] = w2;
    }
}

// ============================================================
// kD: output row (b,j) = segmented weighted sum, same t-order as reference.
// grid (SS, BB) x 192 threads (one float4 column per thread).
// ============================================================
__global__ void kD(const float* __restrict__ x, float* __restrict__ out) {
    int j = blockIdx.x, b = blockIdx.y;
    int i = threadIdx.x;                  // 0..191
    float4* o4 = (float4*)out + (size_t)(b * SS + j) * DD4 + i;
    int F = g_F[b];
    if (j >= F) { *o4 = make_float4(0.f, 0.f, 0.f, 0.f); return; }

    int p1 = g_firepos[b * SS + j];
    int p0 = (j == 0) ? 0 : g_firepos[b * SS + j - 1];
    const float4* x4 = (const float4*)x + (size_t)b * SS * DD4 + i;

    float4 acc = make_float4(0.f, 0.f, 0.f, 0.f);
    int t = p0;
    if (j > 0) {                          // spill a2*h from previous fire step
        float w = g_wspill[b * SS + p0];
        float4 h = __ldg(x4 + (size_t)p0 * DD4);
        acc.x = w * h.x; acc.y = w * h.y; acc.z = w * h.z; acc.w = w * h.w;
        t = p0 + 1;
    }
#pragma unroll 4
    for (; t <= p1; ++t) {                // interior a*h ... then a1*h at fire
        float w = g_wmain[b * SS + t];
        float4 h = __ldg(x4 + (size_t)t * DD4);
        acc.x += w * h.x; acc.y += w * h.y; acc.z += w * h.z; acc.w += w * h.w;
    }
    *o4 = acc;
}

// ============================================================
extern "C" void kernel_launch(void* const* d_in, const int* in_sizes, int n_in,
                              void* d_out, int out_size) {
    const float* x      = (const float*)d_in[0];   // encoder_outputs (B,S,D)
    const int*   lens   = (const int*)  d_in[1];   // encoder_lens (B,)
    const float* conv_w = (const float*)d_in[2];   // (D,D,3)
    const float* conv_b = (const float*)d_in[3];   // (D,)
    const float* lin_w  = (const float*)d_in[4];   // (1,D)
    const float* lin_b  = (const float*)d_in[5];   // (1,)
    float* out = (float*)d_out;
    float* lens_out = (out_size >= BB * SS * DD + BB) ? out + (size_t)BB * SS * DD
                                                      : nullptr;

    kA <<<ROW3 / TPB_A, 256>>>(conv_w, conv_b, lin_w, lin_b);
    kB <<<BB * SS / 8, 256>>>(x, lens);
    kCc<<<BB * CH, 256>>>(lens, lens_out);
    kD <<<dim3(SS, BB), 192>>>(x, out);
}